// round 2
// baseline (speedup 1.0000x reference)
#include <cuda_runtime.h>
#include <cuda_bf16.h>
#include <cstdint>

#define TV 16384
#define V_SZ 1024
#define T_SZ 16
#define B_SZ 256
#define JT 8            // rows of W per CTA
#define THREADS 256     // one thread per batch element

// Each CTA handles JT consecutive rows j of W for ALL 256 batches.
// Per row: cooperative coalesced load of the 64KB row into smem,
// then each thread (= one batch b) gathers its 16 indexed elements and sums.
// Final store: out[b, j0..j0+JT) = 32B contiguous per thread (one DRAM sector).
__global__ void __launch_bounds__(THREADS, 3) gather_sum_relu_kernel(
    const void* __restrict__ x_raw,     // [B, T] int64 or int32 (detected)
    const float* __restrict__ W,        // [TV, TV] row-major
    const float* __restrict__ bias,     // [TV]
    float* __restrict__ out)            // [B, TV]
{
    extern __shared__ float srow[];     // TV floats = 64 KB
    const int b  = threadIdx.x;
    const int j0 = blockIdx.x * JT;

    // ---- Load this thread's 16 gather indices (dtype-robust) ----
    // Interpret as int64 first; valid iff every value is in [0, V).
    // int32 data misread as int64 yields huge values -> fall back to int32.
    const long long* x64 = (const long long*)x_raw;
    const int*       x32 = (const int*)x_raw;
    long long v64[T_SZ];
    bool ok64 = true;
    #pragma unroll
    for (int t = 0; t < T_SZ; t++) {
        v64[t] = x64[b * T_SZ + t];
        if (v64[t] < 0 || v64[t] >= V_SZ) ok64 = false;
    }
    int c[T_SZ];
    #pragma unroll
    for (int t = 0; t < T_SZ; t++) {
        int xi = ok64 ? (int)v64[t] : x32[b * T_SZ + t];
        c[t] = xi + t * V_SZ;
    }

    float acc[JT];

    for (int jj = 0; jj < JT; jj++) {
        // ---- cooperative row load: 16384 floats = 16 float4 per thread ----
        const float4* src = (const float4*)(W + (size_t)(j0 + jj) * TV);
        float4* dst4 = (float4*)srow;
        #pragma unroll
        for (int i = 0; i < TV / 4 / THREADS; i++) {
            dst4[i * THREADS + threadIdx.x] = src[i * THREADS + threadIdx.x];
        }
        __syncthreads();

        // ---- gather + sum for this thread's batch ----
        float s = 0.f;
        #pragma unroll
        for (int t = 0; t < T_SZ; t++) s += srow[c[t]];
        acc[jj] = s;
        __syncthreads();   // protect smem before next row overwrite
    }

    // ---- bias + relu + vectorized 32B store per thread ----
    float4 o0, o1;
    {
        float r[JT];
        #pragma unroll
        for (int jj = 0; jj < JT; jj++) {
            float v = acc[jj] + bias[j0 + jj];
            r[jj] = v > 0.f ? v : 0.f;
        }
        o0 = make_float4(r[0], r[1], r[2], r[3]);
        o1 = make_float4(r[4], r[5], r[6], r[7]);
    }
    float4* o = (float4*)(out + (size_t)b * TV + j0);
    o[0] = o0;
    o[1] = o1;
}

extern "C" void kernel_launch(void* const* d_in, const int* in_sizes, int n_in,
                              void* d_out, int out_size) {
    const void*  x    = d_in[0];                 // [256, 16] int64/int32
    const float* W    = (const float*)d_in[1];   // [16384, 16384]
    const float* bias = (const float*)d_in[2];   // [16384]
    float* out = (float*)d_out;                  // [256, 16384]

    const int smem_bytes = TV * (int)sizeof(float);   // 65536
    static bool attr_set = false;  // idempotent host-side attr; safe to repeat but cache anyway
    if (!attr_set) {
        cudaFuncSetAttribute(gather_sum_relu_kernel,
                             cudaFuncAttributeMaxDynamicSharedMemorySize, smem_bytes);
        attr_set = true;
    }

    dim3 grid(TV / JT);   // 2048 CTAs
    dim3 block(THREADS);  // 256 threads
    gather_sum_relu_kernel<<<grid, block, smem_bytes>>>(x, W, bias, out);
}

// round 3
// speedup vs baseline: 1.0844x; 1.0844x over previous
#include <cuda_runtime.h>
#include <cuda_bf16.h>
#include <cstdint>

#define TV 16384
#define V_SZ 1024
#define T_SZ 16
#define B_SZ 256
#define NSECT 2048          // TV/8 sectors (32B each)
#define JT 8                // W rows per CTA
#define THREADS 256         // one thread per batch element

// Device-global scratch (allocation-free rule).
__device__ int d_nsec;
__device__ int d_sec[NSECT];            // compacted list of needed sector ids
__device__ int d_remap[B_SZ * T_SZ];    // per (b,t): float slot in compacted row

// ---------------------------------------------------------------------------
// Kernel A: build the union-of-needed-sectors compaction + per-entry remap.
// One CTA, 1024 threads. Runs every launch (deterministic, ~µs).
// dtype detection without OOB: read x as int32 only. Genuine int64 data in
// [0,1024) looks like pairs (v, 0); genuine int32 data essentially never does.
// ---------------------------------------------------------------------------
__global__ void build_index_kernel(const void* __restrict__ x_raw) {
    __shared__ int sflag[NSECT];
    __shared__ int sscan[NSECT];
    __shared__ int s_is64;
    const int tid = threadIdx.x;              // 0..1023
    if (tid == 0) s_is64 = 1;
    sflag[tid] = 0; sflag[tid + 1024] = 0;
    __syncthreads();

    const int* x32 = (const int*)x_raw;
    // Check first 2048 logical entries' int64 plausibility (indices < 4096: safe
    // for both int32 (4096 elems) and int64 (8192 int32 words) buffers).
    for (int e = tid; e < 2048; e += 1024) {
        int lo = x32[2 * e], hi = x32[2 * e + 1];
        if (hi != 0 || lo < 0 || lo >= V_SZ) s_is64 = 0;
    }
    __syncthreads();
    const int is64 = s_is64;

    // Mark needed sectors.
    for (int e = tid; e < B_SZ * T_SZ; e += 1024) {
        int xi = is64 ? x32[2 * e] : x32[e];
        int c = xi + (e % T_SZ) * V_SZ;       // e = b*16 + t  ->  t = e%16
        sflag[c >> 3] = 1;
    }
    __syncthreads();

    // Hillis-Steele inclusive scan over 2048 flags with 1024 threads.
    sscan[tid] = sflag[tid];
    sscan[tid + 1024] = sflag[tid + 1024];
    __syncthreads();
    for (int off = 1; off < NSECT; off <<= 1) {
        int v0 = (tid >= off) ? sscan[tid - off] : 0;
        int v1 = sscan[tid + 1024 - off];     // tid+1024 >= off always
        __syncthreads();
        sscan[tid] += v0;
        sscan[tid + 1024] += v1;
        __syncthreads();
    }

    // Compact sector list (slot = exclusive scan = inclusive - 1 where flag==1).
    for (int s = tid; s < NSECT; s += 1024) {
        if (sflag[s]) d_sec[sscan[s] - 1] = s;
    }
    // Per-entry remap into compacted layout.
    for (int e = tid; e < B_SZ * T_SZ; e += 1024) {
        int xi = is64 ? x32[2 * e] : x32[e];
        int c = xi + (e % T_SZ) * V_SZ;
        d_remap[e] = (sscan[c >> 3] - 1) * 8 + (c & 7);
    }
    if (tid == 0) d_nsec = sscan[NSECT - 1];
}

// ---------------------------------------------------------------------------
// Kernel B: per CTA, JT consecutive W rows x all 256 batches.
// Row load fetches ONLY needed sectors via cp.async.cg (L2 -> smem, bypasses
// L1 + registers). Gather uses the precomputed compacted remap.
// ---------------------------------------------------------------------------
__global__ void __launch_bounds__(THREADS, 3) gather_sum_relu_kernel(
    const float* __restrict__ W,        // [TV, TV] row-major
    const float* __restrict__ bias,     // [TV]
    float* __restrict__ out)            // [B, TV]
{
    extern __shared__ float smem[];
    float* buf = smem;                          // up to 16384 floats (64KB)
    int* ssec = (int*)(smem + TV);              // up to 2048 ints (8KB)

    const int tid = threadIdx.x;                // = batch b
    const int j0 = blockIdx.x * JT;
    const int nsec = d_nsec;

    for (int i = tid; i < nsec; i += THREADS) ssec[i] = d_sec[i];

    int rm[T_SZ];
    #pragma unroll
    for (int t = 0; t < T_SZ; t++) rm[t] = d_remap[tid * T_SZ + t];
    __syncthreads();

    const int nchunk = nsec * 2;                // 16B chunks per row
    float acc[JT];

    for (int jj = 0; jj < JT; jj++) {
        const float* rowp = W + (size_t)(j0 + jj) * TV;
        for (int i = tid; i < nchunk; i += THREADS) {
            int s = ssec[i >> 1];
            const float* g = rowp + s * 8 + (i & 1) * 4;
            uint32_t daddr = (uint32_t)__cvta_generic_to_shared(buf + i * 4);
            asm volatile("cp.async.cg.shared.global [%0], [%1], 16;\n"
                         :: "r"(daddr), "l"(g));
        }
        asm volatile("cp.async.commit_group;\n" ::: "memory");
        asm volatile("cp.async.wait_group 0;\n" ::: "memory");
        __syncthreads();

        float s = 0.f;
        #pragma unroll
        for (int t = 0; t < T_SZ; t++) s += buf[rm[t]];
        acc[jj] = s;
        __syncthreads();                        // protect buf before overwrite
    }

    // bias + relu + 32B contiguous store per thread (one DRAM sector)
    float r[JT];
    #pragma unroll
    for (int jj = 0; jj < JT; jj++) {
        float v = acc[jj] + bias[j0 + jj];
        r[jj] = v > 0.f ? v : 0.f;
    }
    float4* o = (float4*)(out + (size_t)tid * TV + j0);
    o[0] = make_float4(r[0], r[1], r[2], r[3]);
    o[1] = make_float4(r[4], r[5], r[6], r[7]);
}

extern "C" void kernel_launch(void* const* d_in, const int* in_sizes, int n_in,
                              void* d_out, int out_size) {
    const void*  x    = d_in[0];                 // [256, 16] int64/int32
    const float* W    = (const float*)d_in[1];   // [16384, 16384]
    const float* bias = (const float*)d_in[2];   // [16384]
    float* out = (float*)d_out;                  // [256, 16384]

    const int smem_bytes = TV * (int)sizeof(float) + NSECT * (int)sizeof(int); // 73728
    static bool attr_set = false;
    if (!attr_set) {
        cudaFuncSetAttribute(gather_sum_relu_kernel,
                             cudaFuncAttributeMaxDynamicSharedMemorySize, smem_bytes);
        attr_set = true;
    }

    build_index_kernel<<<1, 1024>>>(x);
    gather_sum_relu_kernel<<<TV / JT, THREADS, smem_bytes>>>(W, bias, out);
}

// round 4
// speedup vs baseline: 1.0921x; 1.0071x over previous
#include <cuda_runtime.h>
#include <cuda_bf16.h>
#include <cstdint>

#define TV 16384
#define V_SZ 1024
#define T_SZ 16
#define B_SZ 256
#define NSECT 2048          // TV/8 sectors (32B each)
#define JT 8                // W rows per CTA
#define THREADS 256         // one thread per batch element
#define NSTAGE 4            // pipeline stages per row (4 t-slots each)

// Device-global scratch (allocation-free rule).
__device__ int d_nsec;
__device__ int d_sec[NSECT];            // compacted list of needed sector ids
__device__ int d_remap[B_SZ * T_SZ];    // per (b,t): float slot in compacted row
__device__ int d_tstart[T_SZ + 1];      // compacted-slot boundary per t-slot

template<int N> __device__ __forceinline__ void cp_wait() {
    asm volatile("cp.async.wait_group %0;\n" :: "n"(N) : "memory");
}

// ---------------------------------------------------------------------------
// Kernel A: union-of-needed-sectors compaction + per-entry remap + t-slot
// boundaries. One CTA, 1024 threads.
// ---------------------------------------------------------------------------
__global__ void build_index_kernel(const void* __restrict__ x_raw) {
    __shared__ int sflag[NSECT];
    __shared__ int sscan[NSECT];
    __shared__ int s_is64;
    const int tid = threadIdx.x;              // 0..1023
    if (tid == 0) s_is64 = 1;
    sflag[tid] = 0; sflag[tid + 1024] = 0;
    __syncthreads();

    const int* x32 = (const int*)x_raw;
    // int64-vs-int32 detection: int64 values in [0,1024) look like (v, 0) pairs.
    for (int e = tid; e < 2048; e += 1024) {
        int lo = x32[2 * e], hi = x32[2 * e + 1];
        if (hi != 0 || lo < 0 || lo >= V_SZ) s_is64 = 0;
    }
    __syncthreads();
    const int is64 = s_is64;

    // Mark needed sectors.
    for (int e = tid; e < B_SZ * T_SZ; e += 1024) {
        int xi = is64 ? x32[2 * e] : x32[e];
        int c = xi + (e % T_SZ) * V_SZ;       // e = b*16 + t
        sflag[c >> 3] = 1;
    }
    __syncthreads();

    // Hillis-Steele inclusive scan over 2048 flags with 1024 threads.
    sscan[tid] = sflag[tid];
    sscan[tid + 1024] = sflag[tid + 1024];
    __syncthreads();
    for (int off = 1; off < NSECT; off <<= 1) {
        int v0 = (tid >= off) ? sscan[tid - off] : 0;
        int v1 = sscan[tid + 1024 - off];
        __syncthreads();
        sscan[tid] += v0;
        sscan[tid + 1024] += v1;
        __syncthreads();
    }

    // Compact sector list.
    for (int s = tid; s < NSECT; s += 1024) {
        if (sflag[s]) d_sec[sscan[s] - 1] = s;
    }
    // Per-entry remap into compacted layout.
    for (int e = tid; e < B_SZ * T_SZ; e += 1024) {
        int xi = is64 ? x32[2 * e] : x32[e];
        int c = xi + (e % T_SZ) * V_SZ;
        d_remap[e] = (sscan[c >> 3] - 1) * 8 + (c & 7);
    }
    // t-slot boundaries in compacted space (t-slot t owns sectors [t*128,(t+1)*128)).
    if (tid <= T_SZ) {
        d_tstart[tid] = (tid == 0) ? 0 : sscan[tid * (NSECT / T_SZ) - 1];
    }
    if (tid == 0) d_nsec = sscan[NSECT - 1];
}

// ---------------------------------------------------------------------------
// Kernel B: per CTA, JT consecutive W rows x all 256 batches.
// Row load = 4 cp.async stages (4 t-slots each); gather of stage g overlaps
// DRAM streaming of stages g+1..3. Pipe drains only on the last quarter-row.
// ---------------------------------------------------------------------------
__global__ void __launch_bounds__(THREADS, 3) gather_sum_relu_kernel(
    const float* __restrict__ W,        // [TV, TV] row-major
    const float* __restrict__ bias,     // [TV]
    float* __restrict__ out)            // [B, TV]
{
    extern __shared__ float smem[];
    float* buf = smem;                          // up to 16384 floats (64KB)
    int* ssec = (int*)(smem + TV);              // up to 2048 ints (8KB)

    const int tid = threadIdx.x;                // = batch b
    const int j0 = blockIdx.x * JT;
    const int nsec = d_nsec;

    for (int i = tid; i < nsec; i += THREADS) ssec[i] = d_sec[i];

    // Stage boundaries in 16B-chunk units (stage g = t-slots 4g..4g+3).
    int st[NSTAGE + 1];
    #pragma unroll
    for (int g = 0; g <= NSTAGE; g++) st[g] = d_tstart[g * 4] * 2;

    int rm[T_SZ];
    #pragma unroll
    for (int t = 0; t < T_SZ; t++) rm[t] = d_remap[tid * T_SZ + t];
    __syncthreads();

    float acc[JT];

    for (int jj = 0; jj < JT; jj++) {
        const float* rowp = W + (size_t)(j0 + jj) * TV;

        // Issue all 4 stages as separate commit groups.
        #pragma unroll
        for (int g = 0; g < NSTAGE; g++) {
            for (int i = st[g] + tid; i < st[g + 1]; i += THREADS) {
                int s = ssec[i >> 1];
                const float* gp = rowp + s * 8 + (i & 1) * 4;
                uint32_t daddr = (uint32_t)__cvta_generic_to_shared(buf + i * 4);
                asm volatile("cp.async.cg.shared.global [%0], [%1], 16;\n"
                             :: "r"(daddr), "l"(gp));
            }
            asm volatile("cp.async.commit_group;\n" ::: "memory");
        }

        // Gather stage-by-stage while later stages stream in.
        float s = 0.f;
        cp_wait<3>(); __syncthreads();
        #pragma unroll
        for (int t = 0; t < 4; t++)  s += buf[rm[t]];
        cp_wait<2>(); __syncthreads();
        #pragma unroll
        for (int t = 4; t < 8; t++)  s += buf[rm[t]];
        cp_wait<1>(); __syncthreads();
        #pragma unroll
        for (int t = 8; t < 12; t++) s += buf[rm[t]];
        cp_wait<0>(); __syncthreads();
        #pragma unroll
        for (int t = 12; t < 16; t++) s += buf[rm[t]];
        acc[jj] = s;
        __syncthreads();                        // protect buf before overwrite
    }

    // bias + relu + 32B contiguous store per thread (one DRAM sector)
    float r[JT];
    #pragma unroll
    for (int jj = 0; jj < JT; jj++) {
        float v = acc[jj] + bias[j0 + jj];
        r[jj] = v > 0.f ? v : 0.f;
    }
    float4* o = (float4*)(out + (size_t)tid * TV + j0);
    o[0] = make_float4(r[0], r[1], r[2], r[3]);
    o[1] = make_float4(r[4], r[5], r[6], r[7]);
}

extern "C" void kernel_launch(void* const* d_in, const int* in_sizes, int n_in,
                              void* d_out, int out_size) {
    const void*  x    = d_in[0];                 // [256, 16] int64/int32
    const float* W    = (const float*)d_in[1];   // [16384, 16384]
    const float* bias = (const float*)d_in[2];   // [16384]
    float* out = (float*)d_out;                  // [256, 16384]

    const int smem_bytes = TV * (int)sizeof(float) + NSECT * (int)sizeof(int); // 73728
    static bool attr_set = false;
    if (!attr_set) {
        cudaFuncSetAttribute(gather_sum_relu_kernel,
                             cudaFuncAttributeMaxDynamicSharedMemorySize, smem_bytes);
        attr_set = true;
    }

    build_index_kernel<<<1, 1024>>>(x);
    gather_sum_relu_kernel<<<TV / JT, THREADS, smem_bytes>>>(W, bias, out);
}

// round 5
// speedup vs baseline: 1.1118x; 1.0180x over previous
#include <cuda_runtime.h>
#include <cuda_bf16.h>
#include <cstdint>

#define TV 16384
#define V_SZ 1024
#define T_SZ 16
#define B_SZ 256
#define NSECT 2048          // TV/8 sectors (32B each)
#define JT 8                // W rows per CTA
#define THREADS 256         // one thread per batch element
#define HBUF 8192           // floats per half-row buffer (1024 sectors max)

// Device-global scratch (allocation-free rule).
__device__ int d_nsec;
__device__ int d_sec[NSECT];            // compacted list of needed sector ids
__device__ int d_remap[B_SZ * T_SZ];    // per (b,t): float slot in compacted row
__device__ int d_tstart[T_SZ + 1];      // compacted-slot boundary per t-slot

template<int N> __device__ __forceinline__ void cp_wait() {
    asm volatile("cp.async.wait_group %0;\n" :: "n"(N) : "memory");
}
__device__ __forceinline__ void cp_commit() {
    asm volatile("cp.async.commit_group;\n" ::: "memory");
}

// ---------------------------------------------------------------------------
// Kernel A: union-of-needed-sectors compaction + per-entry remap + t-slot
// boundaries. One CTA, 1024 threads.
// ---------------------------------------------------------------------------
__global__ void build_index_kernel(const void* __restrict__ x_raw) {
    __shared__ int sflag[NSECT];
    __shared__ int sscan[NSECT];
    __shared__ int s_is64;
    const int tid = threadIdx.x;              // 0..1023
    if (tid == 0) s_is64 = 1;
    sflag[tid] = 0; sflag[tid + 1024] = 0;
    __syncthreads();

    const int* x32 = (const int*)x_raw;
    // int64-vs-int32 detection: int64 values in [0,1024) look like (v, 0) pairs.
    for (int e = tid; e < 2048; e += 1024) {
        int lo = x32[2 * e], hi = x32[2 * e + 1];
        if (hi != 0 || lo < 0 || lo >= V_SZ) s_is64 = 0;
    }
    __syncthreads();
    const int is64 = s_is64;

    // Mark needed sectors.
    for (int e = tid; e < B_SZ * T_SZ; e += 1024) {
        int xi = is64 ? x32[2 * e] : x32[e];
        int c = xi + (e % T_SZ) * V_SZ;       // e = b*16 + t
        sflag[c >> 3] = 1;
    }
    __syncthreads();

    // Hillis-Steele inclusive scan over 2048 flags with 1024 threads.
    sscan[tid] = sflag[tid];
    sscan[tid + 1024] = sflag[tid + 1024];
    __syncthreads();
    for (int off = 1; off < NSECT; off <<= 1) {
        int v0 = (tid >= off) ? sscan[tid - off] : 0;
        int v1 = sscan[tid + 1024 - off];
        __syncthreads();
        sscan[tid] += v0;
        sscan[tid + 1024] += v1;
        __syncthreads();
    }

    // Compact sector list.
    for (int s = tid; s < NSECT; s += 1024) {
        if (sflag[s]) d_sec[sscan[s] - 1] = s;
    }
    // Per-entry remap into compacted layout.
    for (int e = tid; e < B_SZ * T_SZ; e += 1024) {
        int xi = is64 ? x32[2 * e] : x32[e];
        int c = xi + (e % T_SZ) * V_SZ;
        d_remap[e] = (sscan[c >> 3] - 1) * 8 + (c & 7);
    }
    // t-slot boundaries in compacted space (t-slot t owns sectors [t*128,(t+1)*128)).
    if (tid <= T_SZ) {
        d_tstart[tid] = (tid == 0) ? 0 : sscan[tid * (NSECT / T_SZ) - 1];
    }
    if (tid == 0) d_nsec = sscan[NSECT - 1];
}

// ---------------------------------------------------------------------------
// Kernel B: per CTA, JT consecutive W rows x all 256 batches.
// Half-row (8 t-slots, <=32KB) double buffering: while gathering half k,
// half k+1 is streaming from DRAM; half k+2 is issued right after the gather.
// The cp.async pipe drains only once per CTA (at the final half).
// ---------------------------------------------------------------------------
__global__ void __launch_bounds__(THREADS, 3) gather_sum_relu_kernel(
    const float* __restrict__ W,        // [TV, TV] row-major
    const float* __restrict__ bias,     // [TV]
    float* __restrict__ out)            // [B, TV]
{
    extern __shared__ float smem[];
    float* buf0 = smem;                         // HBUF floats (t-slots 0..7)
    float* buf1 = smem + HBUF;                  // HBUF floats (t-slots 8..15)
    unsigned short* ssec = (unsigned short*)(smem + 2 * HBUF);  // NSECT u16

    const int tid = threadIdx.x;                // = batch b
    const int j0 = blockIdx.x * JT;
    const int h1 = d_tstart[8];                 // first-half sector count
    const int h2 = d_nsec;                      // total sector count

    for (int i = tid; i < h2; i += THREADS) ssec[i] = (unsigned short)d_sec[i];

    int off[T_SZ];
    {
        const int sub = h1 * 8;
        #pragma unroll
        for (int t = 0; t < T_SZ; t++) {
            int rm = d_remap[tid * T_SZ + t];
            off[t] = (t < 8) ? rm : (rm - sub);
        }
    }
    __syncthreads();

    // Issue one half-row (global half index m) as one cp.async group.
    auto issue = [&](int m) {
        const int hh = m & 1;
        const float* rowp = W + (size_t)(j0 + (m >> 1)) * TV;
        float* bdst = hh ? buf1 : buf0;
        const int c0 = (hh ? h1 : 0) * 2;       // 16B-chunk range
        const int c1 = (hh ? h2 : h1) * 2;
        const int fbase = (hh ? h1 : 0) * 8;    // float base of this half
        for (int i = c0 + tid; i < c1; i += THREADS) {
            int s = ssec[i >> 1];
            const float* gp = rowp + s * 8 + (i & 1) * 4;
            uint32_t daddr = (uint32_t)__cvta_generic_to_shared(bdst + (i * 4 - fbase));
            asm volatile("cp.async.cg.shared.global [%0], [%1], 16;\n"
                         :: "r"(daddr), "l"(gp));
        }
        cp_commit();
    };

    issue(0);
    issue(1);

    float acc[JT];
    #pragma unroll 2
    for (int k = 0; k < 2 * JT; k++) {
        if (k == 2 * JT - 1) cp_wait<0>(); else cp_wait<1>();
        __syncthreads();
        float s = (k & 1) ? acc[k >> 1] : 0.f;
        if ((k & 1) == 0) {
            #pragma unroll
            for (int t = 0; t < 8; t++) s += buf0[off[t]];
        } else {
            #pragma unroll
            for (int t = 8; t < 16; t++) s += buf1[off[t]];
        }
        acc[k >> 1] = s;
        __syncthreads();                        // buffer free before re-issue
        if (k + 2 < 2 * JT) issue(k + 2);
    }

    // bias + relu + 32B contiguous store per thread (one DRAM sector)
    float r[JT];
    #pragma unroll
    for (int jj = 0; jj < JT; jj++) {
        float v = acc[jj] + bias[j0 + jj];
        r[jj] = v > 0.f ? v : 0.f;
    }
    float4* o = (float4*)(out + (size_t)tid * TV + j0);
    o[0] = make_float4(r[0], r[1], r[2], r[3]);
    o[1] = make_float4(r[4], r[5], r[6], r[7]);
}

extern "C" void kernel_launch(void* const* d_in, const int* in_sizes, int n_in,
                              void* d_out, int out_size) {
    const void*  x    = d_in[0];                 // [256, 16] int64/int32
    const float* W    = (const float*)d_in[1];   // [16384, 16384]
    const float* bias = (const float*)d_in[2];   // [16384]
    float* out = (float*)d_out;                  // [256, 16384]

    // 2 half-row buffers (32KB each) + u16 sector list (4KB) = 68KB -> 3 CTAs/SM
    const int smem_bytes = 2 * HBUF * (int)sizeof(float) + NSECT * (int)sizeof(unsigned short);
    static bool attr_set = false;
    if (!attr_set) {
        cudaFuncSetAttribute(gather_sum_relu_kernel,
                             cudaFuncAttributeMaxDynamicSharedMemorySize, smem_bytes);
        attr_set = true;
    }

    build_index_kernel<<<1, 1024>>>(x);
    gather_sum_relu_kernel<<<TV / JT, THREADS, smem_bytes>>>(W, bias, out);
}